// round 7
// baseline (speedup 1.0000x reference)
#include <cuda_runtime.h>
#include <cstdint>

// ---------------------------------------------------------------------------
// GungnirHalfKA (NNUE) batched eval, GB300 sm_103a — Round 7
// R6 + two-level add tree: pair rows in packed int8 (vadd4), widen once.
// ---------------------------------------------------------------------------

#define FT_IN   45056
#define FT_OUT  1024
#define NB_MAX  8

__device__ signed char g_ftq[(size_t)FT_IN * FT_OUT];   // 46 MB, int8-exact
__device__ signed char g_fc0q[NB_MAX * 16 * FT_OUT];    // 128 KB, int8-exact
__device__ unsigned    g_bq[FT_OUT / 2];                // bias, 2x i16 packed

__device__ __forceinline__ float q8f(float x) {
    return fminf(fmaxf(rintf(x), -128.f), 127.f);
}
__device__ __forceinline__ float q16f(float x) {
    return fminf(fmaxf(rintf(x), -32768.f), 32767.f);
}
__device__ __forceinline__ float q32f(float x) {
    return fminf(fmaxf(rintf(x), -2147483648.f), 2147483647.f);
}
__device__ __forceinline__ float clip127(float x) {
    return fminf(fmaxf(x, 0.f), 127.f);
}

// Widen 4 packed int8 -> 2x(2x int16) and accumulate (2 prmt + 2 vadd2).
__device__ __forceinline__ void acc4(unsigned* a, unsigned v) {
    unsigned lo, hi;
    asm("prmt.b32 %0, %1, 0, 0x9180;" : "=r"(lo) : "r"(v));
    asm("prmt.b32 %0, %1, 0, 0xB3A2;" : "=r"(hi) : "r"(v));
    a[0] = __vadd2(a[0], lo);
    a[1] = __vadd2(a[1], hi);
}
__device__ __forceinline__ void acc16(unsigned* acc, const int4& v) {
    acc4(acc + 0, (unsigned)v.x);
    acc4(acc + 2, (unsigned)v.y);
    acc4(acc + 4, (unsigned)v.z);
    acc4(acc + 6, (unsigned)v.w);
}
// Pair two rows in packed int8 (exact: |val|<=~30 each), widen once.
__device__ __forceinline__ void accPair(unsigned* acc, const int4& a, const int4& b) {
    int4 p;
    p.x = (int)__vadd4((unsigned)a.x, (unsigned)b.x);
    p.y = (int)__vadd4((unsigned)a.y, (unsigned)b.y);
    p.z = (int)__vadd4((unsigned)a.z, (unsigned)b.z);
    p.w = (int)__vadd4((unsigned)a.w, (unsigned)b.w);
    acc16(acc, p);
}

// ---- precompute: ft_weight -> int8, fc0_w -> int8, ft_bias -> packed i16 --
#define FT_BLOCKS  (FT_IN)
#define FC0_ELEMS  (NB_MAX * 16 * FT_OUT)
#define FC0_BLOCKS (FC0_ELEMS / 1024)

__global__ void cvt_kernel(const float* __restrict__ ftw,
                           const float* __restrict__ f0w,
                           const float* __restrict__ ftb) {
    int blk = blockIdx.x;
    if (blk < FT_BLOCKS) {
        int i = blk * 256 + threadIdx.x;
        float4 v = __ldcs(reinterpret_cast<const float4*>(ftw) + i);
        char4 c;
        c.x = (signed char)q8f(v.x);
        c.y = (signed char)q8f(v.y);
        c.z = (signed char)q8f(v.z);
        c.w = (signed char)q8f(v.w);
        reinterpret_cast<char4*>(g_ftq)[i] = c;
    } else if (blk < FT_BLOCKS + FC0_BLOCKS) {
        int i = (blk - FT_BLOCKS) * 256 + threadIdx.x;
        float4 v = __ldcs(reinterpret_cast<const float4*>(f0w) + i);
        char4 c;
        c.x = (signed char)q8f(v.x);
        c.y = (signed char)q8f(v.y);
        c.z = (signed char)q8f(v.z);
        c.w = (signed char)q8f(v.w);
        reinterpret_cast<char4*>(g_fc0q)[i] = c;
    } else {
        int t = threadIdx.x;
        #pragma unroll
        for (int h = 0; h < 2; h++) {
            int w = t * 2 + h;                 // word 0..511
            int b0 = (int)q16f(ftb[w * 2]);
            int b1 = (int)q16f(ftb[w * 2 + 1]);
            g_bq[w] = (unsigned)(b0 & 0xFFFF) | ((unsigned)b1 << 16);
        }
    }
}

// ---- main fused kernel: one 64-thread CTA per batch item ------------------
__global__ __launch_bounds__(64, 20)
void nnue_kernel(const int* __restrict__ wf,  const int* __restrict__ wo,
                 const int* __restrict__ bf,  const int* __restrict__ bo,
                 const int* __restrict__ stm, const int* __restrict__ bucket,
                 const float* __restrict__ psq,
                 const float* __restrict__ fc0b, const float* __restrict__ fc1w,
                 const float* __restrict__ fc1b, const float* __restrict__ fc2w,
                 const float* __restrict__ fc2b,
                 float* __restrict__ out, int nfeat_total, int nb)
{
    const int b    = blockIdx.x;
    const int tid  = threadIdx.x;
    const int wid  = tid >> 5;
    const int lane = tid & 31;

    __shared__ __align__(16) int      s_wf[128], s_bf[128];
    __shared__ __align__(16) unsigned s_S[FT_OUT / 4];   // clipped acc_stm u8
    __shared__ __align__(16) unsigned s_O[FT_OUT / 4];   // clipped acc_opp u8
    __shared__ __align__(16) unsigned short s_p[FT_OUT]; // pair products u16
    __shared__ float s_o0[16];
    __shared__ float s_slab[32];
    __shared__ float s_psqt, s_scalar;
    __shared__ int   s_meta[4];

    if (tid == 0) {
        int ws = wo[b];
        int we = (b + 1 < nb) ? wo[b + 1] : nfeat_total;
        int bs = bo[b];
        int be = (b + 1 < nb) ? bo[b + 1] : nfeat_total;
        s_meta[0] = ws; s_meta[1] = min(we - ws, 128);
        s_meta[2] = bs; s_meta[3] = min(be - bs, 128);
    }
    __syncthreads();
    const int ws  = s_meta[0], nw  = s_meta[1];
    const int bs  = s_meta[2], nbf = s_meta[3];

    for (int i = tid; i < nw;  i += 64) s_wf[i] = wf[ws + i];
    for (int i = tid; i < nbf; i += 64) s_bf[i] = bf[bs + i];
    __syncthreads();

    const int st = stm[b];
    const int bk = bucket[b];
    const int d0 = tid * 16;

    // ---- gather both sides; clip+pack to u8, single STS.128 per side -----
    #pragma unroll
    for (int side = 0; side < 2; side++) {
        const int* feats = side ? s_bf : s_wf;
        const int  n     = side ? nbf  : nw;
        unsigned acc[8] = {0,0,0,0,0,0,0,0};

        int f = 0;
        for (; f + 8 <= n; f += 8) {
            // Batch 8 independent LDG.128; consume as 4 int8 pairs.
            int4 ix0 = *reinterpret_cast<const int4*>(feats + f);
            int4 ix1 = *reinterpret_cast<const int4*>(feats + f + 4);
            int4 v0 = __ldcg(reinterpret_cast<const int4*>(g_ftq + ((size_t)ix0.x << 10) + d0));
            int4 v1 = __ldcg(reinterpret_cast<const int4*>(g_ftq + ((size_t)ix0.y << 10) + d0));
            int4 v2 = __ldcg(reinterpret_cast<const int4*>(g_ftq + ((size_t)ix0.z << 10) + d0));
            int4 v3 = __ldcg(reinterpret_cast<const int4*>(g_ftq + ((size_t)ix0.w << 10) + d0));
            int4 v4 = __ldcg(reinterpret_cast<const int4*>(g_ftq + ((size_t)ix1.x << 10) + d0));
            int4 v5 = __ldcg(reinterpret_cast<const int4*>(g_ftq + ((size_t)ix1.y << 10) + d0));
            int4 v6 = __ldcg(reinterpret_cast<const int4*>(g_ftq + ((size_t)ix1.z << 10) + d0));
            int4 v7 = __ldcg(reinterpret_cast<const int4*>(g_ftq + ((size_t)ix1.w << 10) + d0));
            accPair(acc, v0, v1);
            accPair(acc, v2, v3);
            accPair(acc, v4, v5);
            accPair(acc, v6, v7);
        }
        for (; f + 2 <= n; f += 2) {
            const int4 va = __ldcg(reinterpret_cast<const int4*>(
                g_ftq + ((size_t)feats[f] << 10) + d0));
            const int4 vb = __ldcg(reinterpret_cast<const int4*>(
                g_ftq + ((size_t)feats[f + 1] << 10) + d0));
            accPair(acc, va, vb);
        }
        if (f < n) {
            const int4 v = __ldcg(reinterpret_cast<const int4*>(
                g_ftq + ((size_t)feats[f] << 10) + d0));
            acc16(acc, v);
        }

        // Bias loaded HERE (not live across the loop): 2x LDG.128, L2-hot.
        const uint4 bq0 = reinterpret_cast<const uint4*>(g_bq)[tid * 2];
        const uint4 bq1 = reinterpret_cast<const uint4*>(g_bq)[tid * 2 + 1];
        const unsigned biasp[8] = {bq0.x, bq0.y, bq0.z, bq0.w,
                                   bq1.x, bq1.y, bq1.z, bq1.w};

        // +bias, clip to [0,127], pack 16 dims -> uint4, one STS.128.
        unsigned pw[4];
        #pragma unroll
        for (int j = 0; j < 4; j++) {
            unsigned a01 = __vadd2(acc[2*j],     biasp[2*j]);
            unsigned a23 = __vadd2(acc[2*j + 1], biasp[2*j + 1]);
            a01 = __vmins2(__vmaxs2(a01, 0u), 0x007F007Fu);
            a23 = __vmins2(__vmaxs2(a23, 0u), 0x007F007Fu);
            pw[j] = __byte_perm(a01, a23, 0x6420);
        }
        // white(side0) -> stm? opp : stm ; black(side1) -> stm? stm : opp
        unsigned* dst = (side ^ st) ? s_O : s_S;
        reinterpret_cast<uint4*>(dst)[tid] = make_uint4(pw[0], pw[1], pw[2], pw[3]);
    }
    __syncthreads();

    // ---- pairwise products (u16-exact), conflict-free --------------------
    #pragma unroll
    for (int h = 0; h < 2; h++) {
        int w = tid + h * 64;                  // word 0..127 (4 dims)
        unsigned a = s_S[w], c = s_S[w + 128];
        uint2 stv;
        stv.x = ((a & 0xFFu) * (c & 0xFFu)) |
                ((((a >> 8) & 0xFFu) * ((c >> 8) & 0xFFu)) << 16);
        stv.y = (((a >> 16) & 0xFFu) * ((c >> 16) & 0xFFu)) |
                (((a >> 24) * (c >> 24)) << 16);
        *reinterpret_cast<uint2*>(s_p + 4 * w) = stv;

        unsigned ao = s_O[w], co = s_O[w + 128];
        uint2 stw;
        stw.x = ((ao & 0xFFu) * (co & 0xFFu)) |
                ((((ao >> 8) & 0xFFu) * ((co >> 8) & 0xFFu)) << 16);
        stw.y = (((ao >> 16) & 0xFFu) * ((co >> 16) & 0xFFu)) |
                (((ao >> 24) * (co >> 24)) << 16);
        *reinterpret_cast<uint2*>(s_p + 512 + 4 * w) = stw;
    }
    __syncthreads();

    // ---- fc0: 16 x 1024 matvec; dp2a (s16 x s8), exact int32 -------------
    for (int o = wid; o < 16; o += 2) {
        const signed char* wrow = g_fc0q + ((bk * 16 + o) << 10);
        int isum = 0;
        #pragma unroll
        for (int c = 0; c < 4; c++) {
            int idx = (c * 32 + lane) * 8;                 // 8 dims
            uint4 pv = *reinterpret_cast<const uint4*>(s_p + idx);
            int2  wv = *reinterpret_cast<const int2*>(wrow + idx);
            isum = __dp2a_lo((int)pv.x, wv.x, isum);
            isum = __dp2a_hi((int)pv.y, wv.x, isum);
            isum = __dp2a_lo((int)pv.z, wv.y, isum);
            isum = __dp2a_hi((int)pv.w, wv.y, isum);
        }
        #pragma unroll
        for (int off = 16; off; off >>= 1)
            isum += __shfl_down_sync(0xffffffffu, isum, off);
        if (lane == 0)
            s_o0[o] = (float)isum * (1.f / 128.f) + q32f(fc0b[bk * 16 + o]);
    }
    __syncthreads();

    // ---- warp 1: psqt; warp 0: slab -> fc1 -> fc2 + skip -----------------
    if (wid == 1) {
        float ps = 0.f;
        for (int i = lane; i < nw;  i += 32)
            ps += q32f(psq[(size_t)s_wf[i] * 8 + bk]);
        for (int i = lane; i < nbf; i += 32)
            ps -= q32f(psq[(size_t)s_bf[i] * 8 + bk]);
        #pragma unroll
        for (int off = 16; off; off >>= 1)
            ps += __shfl_down_sync(0xffffffffu, ps, off);
        if (lane == 0) s_psqt = (st ? -ps : ps) * 0.5f;
    } else {
        float sl = 0.f;
        if (lane < 15) {
            float v = s_o0[lane];
            sl = clip127(v * v * (1.f / 524288.f));       // 1<<19
        } else if (lane < 30) {
            float v = s_o0[lane - 15];
            sl = clip127(v * (1.f / 64.f));
        }
        s_slab[lane] = sl;
        __syncwarp();

        const float* w1 = fc1w + (size_t)(bk * 32 + lane) * 32;
        float o1 = 0.f;
        #pragma unroll
        for (int k = 0; k < 32; k++)
            o1 += s_slab[k] * q8f(w1[k]);
        o1 += q32f(fc1b[bk * 32 + lane]);

        float a1 = clip127(o1 * (1.f / 64.f));
        float p  = a1 * q8f(fc2w[bk * 32 + lane]);
        #pragma unroll
        for (int off = 16; off; off >>= 1)
            p += __shfl_down_sync(0xffffffffu, p, off);
        if (lane == 0) {
            float scalar = p + q32f(fc2b[bk]);
            float skip   = s_o0[15] * (9600.f / 8128.f);
            s_scalar = scalar + skip;
        }
    }
    __syncthreads();

    if (tid == 0)
        out[b] = (s_psqt + s_scalar) * (1.f / 16.f);
}

extern "C" void kernel_launch(void* const* d_in, const int* in_sizes, int n_in,
                              void* d_out, int out_size)
{
    const int*   wf   = (const int*)d_in[0];
    const int*   wo   = (const int*)d_in[1];
    const int*   bfi  = (const int*)d_in[2];
    const int*   bo   = (const int*)d_in[3];
    const int*   stm  = (const int*)d_in[4];
    const int*   bkt  = (const int*)d_in[5];
    const float* ftw  = (const float*)d_in[6];
    const float* ftb  = (const float*)d_in[7];
    const float* psq  = (const float*)d_in[8];
    const float* f0w  = (const float*)d_in[9];
    const float* f0b  = (const float*)d_in[10];
    const float* f1w  = (const float*)d_in[11];
    const float* f1b  = (const float*)d_in[12];
    const float* f2w  = (const float*)d_in[13];
    const float* f2b  = (const float*)d_in[14];
    float* out = (float*)d_out;

    const int nb = in_sizes[4];
    const int nfeat_total = in_sizes[0];

    cvt_kernel<<<FT_BLOCKS + FC0_BLOCKS + 1, 256>>>(ftw, f0w, ftb);

    nnue_kernel<<<nb, 64>>>(wf, wo, bfi, bo, stm, bkt,
                            psq, f0b, f1w, f1b, f2w, f2b,
                            out, nfeat_total, nb);
}

// round 10
// speedup vs baseline: 1.2200x; 1.2200x over previous
#include <cuda_runtime.h>
#include <cstdint>

// ---------------------------------------------------------------------------
// GungnirHalfKA (NNUE) batched eval, GB300 sm_103a — Round 9
// R8 with dp2a overload fix: int8 gather + register-resident fc0 (REDUX)
// + int8 fc1 + psqt zero-skip flag.
// ---------------------------------------------------------------------------

#define FT_IN   45056
#define FT_OUT  1024
#define NB_MAX  8

__device__ signed char g_ftq[(size_t)FT_IN * FT_OUT];   // 46 MB, int8-exact
__device__ signed char g_fc0q[NB_MAX * 16 * FT_OUT];    // 128 KB, int8-exact
__device__ signed char g_fc1q[NB_MAX * 32 * 32];        // 8 KB, int8-exact
__device__ unsigned    g_bq[FT_OUT / 2];                // ft bias, 2x i16 packed
__device__ int         g_psq_nz;                        // psqt nonzero flag

__device__ __forceinline__ float q8f(float x) {
    return fminf(fmaxf(rintf(x), -128.f), 127.f);
}
__device__ __forceinline__ float q16f(float x) {
    return fminf(fmaxf(rintf(x), -32768.f), 32767.f);
}
__device__ __forceinline__ float q32f(float x) {
    return fminf(fmaxf(rintf(x), -2147483648.f), 2147483647.f);
}
__device__ __forceinline__ float clip127(float x) {
    return fminf(fmaxf(x, 0.f), 127.f);
}

// Widen 4 packed int8 -> 2x(2x int16) and accumulate.
__device__ __forceinline__ void acc4(unsigned* a, unsigned v) {
    unsigned lo, hi;
    asm("prmt.b32 %0, %1, 0, 0x9180;" : "=r"(lo) : "r"(v));
    asm("prmt.b32 %0, %1, 0, 0xB3A2;" : "=r"(hi) : "r"(v));
    a[0] = __vadd2(a[0], lo);
    a[1] = __vadd2(a[1], hi);
}
__device__ __forceinline__ void acc16(unsigned* acc, const int4& v) {
    acc4(acc + 0, (unsigned)v.x);
    acc4(acc + 2, (unsigned)v.y);
    acc4(acc + 4, (unsigned)v.z);
    acc4(acc + 6, (unsigned)v.w);
}

// 4 byte-pair products (u8*u8 <= 16129, fits positive s16) -> 2 packed words.
__device__ __forceinline__ void mulbytes(unsigned a, unsigned c,
                                         int& lo, int& hi) {
    lo = (int)(((a & 0xFFu) * (c & 0xFFu)) |
               ((((a >> 8) & 0xFFu) * ((c >> 8) & 0xFFu)) << 16));
    hi = (int)((((a >> 16) & 0xFFu) * ((c >> 16) & 0xFFu)) |
               (((a >> 24) * (c >> 24)) << 16));
}

// signed byte j of word w -> float
__device__ __forceinline__ float sb2f(unsigned w, int j) {
    return (float)((int)(w << (24 - 8 * j)) >> 24);
}

// ---- precompute: ft/fc0/fc1 -> int8, ft_bias -> packed i16 ----------------
#define FT_BLOCKS  (FT_IN)
#define FC0_ELEMS  (NB_MAX * 16 * FT_OUT)
#define FC0_BLOCKS (FC0_ELEMS / 1024)          /* 128 */
#define FC1_ELEMS  (NB_MAX * 32 * 32)          /* 8192 */
#define FC1_BLOCKS (FC1_ELEMS / 1024)          /* 8 */

__global__ void cvt_kernel(const float* __restrict__ ftw,
                           const float* __restrict__ f0w,
                           const float* __restrict__ f1w,
                           const float* __restrict__ ftb) {
    int blk = blockIdx.x;
    if (blk < FT_BLOCKS) {
        int i = blk * 256 + threadIdx.x;
        float4 v = __ldcs(reinterpret_cast<const float4*>(ftw) + i);
        char4 c;
        c.x = (signed char)q8f(v.x);
        c.y = (signed char)q8f(v.y);
        c.z = (signed char)q8f(v.z);
        c.w = (signed char)q8f(v.w);
        reinterpret_cast<char4*>(g_ftq)[i] = c;
    } else if (blk < FT_BLOCKS + FC0_BLOCKS) {
        int i = (blk - FT_BLOCKS) * 256 + threadIdx.x;
        float4 v = __ldcs(reinterpret_cast<const float4*>(f0w) + i);
        char4 c;
        c.x = (signed char)q8f(v.x);
        c.y = (signed char)q8f(v.y);
        c.z = (signed char)q8f(v.z);
        c.w = (signed char)q8f(v.w);
        reinterpret_cast<char4*>(g_fc0q)[i] = c;
    } else if (blk < FT_BLOCKS + FC0_BLOCKS + FC1_BLOCKS) {
        int i = (blk - FT_BLOCKS - FC0_BLOCKS) * 256 + threadIdx.x;
        float4 v = __ldcs(reinterpret_cast<const float4*>(f1w) + i);
        char4 c;
        c.x = (signed char)q8f(v.x);
        c.y = (signed char)q8f(v.y);
        c.z = (signed char)q8f(v.z);
        c.w = (signed char)q8f(v.w);
        reinterpret_cast<char4*>(g_fc1q)[i] = c;
    } else {
        int t = threadIdx.x;
        #pragma unroll
        for (int h = 0; h < 2; h++) {
            int w = t * 2 + h;                 // word 0..511
            int b0 = (int)q16f(ftb[w * 2]);
            int b1 = (int)q16f(ftb[w * 2 + 1]);
            g_bq[w] = (unsigned)(b0 & 0xFFFF) | ((unsigned)b1 << 16);
        }
    }
}

// ---- psqt zero-scan: single block, writes flag (deterministic) ------------
__global__ void psq_flag_kernel(const float* __restrict__ psq, int n) {
    int any = 0;
    int n4 = n >> 2;
    for (int i = threadIdx.x; i < n4; i += blockDim.x) {
        float4 v = __ldcs(reinterpret_cast<const float4*>(psq) + i);
        any |= (v.x != 0.f) | (v.y != 0.f) | (v.z != 0.f) | (v.w != 0.f);
    }
    for (int i = n4 * 4 + threadIdx.x; i < n; i += blockDim.x)
        any |= (psq[i] != 0.f);
    int r = __syncthreads_or(any);
    if (threadIdx.x == 0) g_psq_nz = r;
}

// ---- main fused kernel: one 64-thread CTA per batch item ------------------
__global__ __launch_bounds__(64, 20)
void nnue_kernel(const int* __restrict__ wf,  const int* __restrict__ wo,
                 const int* __restrict__ bf,  const int* __restrict__ bo,
                 const int* __restrict__ stm, const int* __restrict__ bucket,
                 const float* __restrict__ psq,
                 const float* __restrict__ fc0b,
                 const float* __restrict__ fc1b, const float* __restrict__ fc2w,
                 const float* __restrict__ fc2b,
                 float* __restrict__ out, int nfeat_total, int nb)
{
    const int b    = blockIdx.x;
    const int tid  = threadIdx.x;
    const int wid  = tid >> 5;
    const int lane = tid & 31;

    __shared__ __align__(16) int      s_wf[128], s_bf[128];
    __shared__ __align__(16) unsigned s_S[FT_OUT / 4];   // clipped acc_stm u8
    __shared__ __align__(16) unsigned s_O[FT_OUT / 4];   // clipped acc_opp u8
    __shared__ int   s_fc0p[32];                         // per-warp fc0 partials
    __shared__ float s_o0[16];
    __shared__ float s_slab[32];
    __shared__ float s_psqt, s_scalar;
    __shared__ int   s_meta[4];

    if (tid == 0) {
        int ws = wo[b];
        int we = (b + 1 < nb) ? wo[b + 1] : nfeat_total;
        int bs = bo[b];
        int be = (b + 1 < nb) ? bo[b + 1] : nfeat_total;
        s_meta[0] = ws; s_meta[1] = min(we - ws, 128);
        s_meta[2] = bs; s_meta[3] = min(be - bs, 128);
    }
    __syncthreads();
    const int ws  = s_meta[0], nw  = s_meta[1];
    const int bs  = s_meta[2], nbf = s_meta[3];

    for (int i = tid; i < nw;  i += 64) s_wf[i] = wf[ws + i];
    for (int i = tid; i < nbf; i += 64) s_bf[i] = bf[bs + i];
    __syncthreads();

    const int st = stm[b];
    const int bk = bucket[b];
    const int d0 = tid * 16;

    // ---- gather both sides; clip+pack to u8, single STS.128 per side -----
    #pragma unroll
    for (int side = 0; side < 2; side++) {
        const int* feats = side ? s_bf : s_wf;
        const int  n     = side ? nbf  : nw;
        unsigned acc[8] = {0,0,0,0,0,0,0,0};

        int f = 0;
        for (; f + 8 <= n; f += 8) {
            int4 ix0 = *reinterpret_cast<const int4*>(feats + f);
            int4 ix1 = *reinterpret_cast<const int4*>(feats + f + 4);
            int4 v0 = __ldcg(reinterpret_cast<const int4*>(g_ftq + ((size_t)ix0.x << 10) + d0));
            int4 v1 = __ldcg(reinterpret_cast<const int4*>(g_ftq + ((size_t)ix0.y << 10) + d0));
            int4 v2 = __ldcg(reinterpret_cast<const int4*>(g_ftq + ((size_t)ix0.z << 10) + d0));
            int4 v3 = __ldcg(reinterpret_cast<const int4*>(g_ftq + ((size_t)ix0.w << 10) + d0));
            int4 v4 = __ldcg(reinterpret_cast<const int4*>(g_ftq + ((size_t)ix1.x << 10) + d0));
            int4 v5 = __ldcg(reinterpret_cast<const int4*>(g_ftq + ((size_t)ix1.y << 10) + d0));
            int4 v6 = __ldcg(reinterpret_cast<const int4*>(g_ftq + ((size_t)ix1.z << 10) + d0));
            int4 v7 = __ldcg(reinterpret_cast<const int4*>(g_ftq + ((size_t)ix1.w << 10) + d0));
            acc16(acc, v0); acc16(acc, v1); acc16(acc, v2); acc16(acc, v3);
            acc16(acc, v4); acc16(acc, v5); acc16(acc, v6); acc16(acc, v7);
        }
        for (; f < n; f++) {
            const int4 v = __ldcg(reinterpret_cast<const int4*>(
                g_ftq + ((size_t)feats[f] << 10) + d0));
            acc16(acc, v);
        }

        const uint4 bq0 = reinterpret_cast<const uint4*>(g_bq)[tid * 2];
        const uint4 bq1 = reinterpret_cast<const uint4*>(g_bq)[tid * 2 + 1];
        const unsigned biasp[8] = {bq0.x, bq0.y, bq0.z, bq0.w,
                                   bq1.x, bq1.y, bq1.z, bq1.w};

        unsigned pw[4];
        #pragma unroll
        for (int j = 0; j < 4; j++) {
            unsigned a01 = __vadd2(acc[2*j],     biasp[2*j]);
            unsigned a23 = __vadd2(acc[2*j + 1], biasp[2*j + 1]);
            a01 = __vmins2(__vmaxs2(a01, 0u), 0x007F007Fu);
            a23 = __vmins2(__vmaxs2(a23, 0u), 0x007F007Fu);
            pw[j] = __byte_perm(a01, a23, 0x6420);
        }
        unsigned* dst = (side ^ st) ? s_O : s_S;
        reinterpret_cast<uint4*>(dst)[tid] = make_uint4(pw[0], pw[1], pw[2], pw[3]);
    }
    __syncthreads();

    // ---- pairwise products for MY 16 dims, kept in registers -------------
    // Thread t owns product dims [16t, 16t+16): t<32 from S-half, t>=32 from O.
    int prod[8];
    {
        const unsigned* src = (tid < 32) ? s_S : s_O;
        const int tt = tid & 31;
        uint4 A = *reinterpret_cast<const uint4*>(src + 4 * tt);
        uint4 C = *reinterpret_cast<const uint4*>(src + 4 * tt + 128);
        mulbytes(A.x, C.x, prod[0], prod[1]);
        mulbytes(A.y, C.y, prod[2], prod[3]);
        mulbytes(A.z, C.z, prod[4], prod[5]);
        mulbytes(A.w, C.w, prod[6], prod[7]);
    }

    // ---- fc0: all threads, all 16 outputs over own dims; REDUX per warp --
    {
        const signed char* wbase = g_fc0q + (bk << 14) + 16 * tid;
        #pragma unroll
        for (int o = 0; o < 16; o++) {
            int4 wv = *reinterpret_cast<const int4*>(wbase + (o << 10));
            int s = 0;
            s = __dp2a_lo(prod[0], wv.x, s);
            s = __dp2a_hi(prod[1], wv.x, s);
            s = __dp2a_lo(prod[2], wv.y, s);
            s = __dp2a_hi(prod[3], wv.y, s);
            s = __dp2a_lo(prod[4], wv.z, s);
            s = __dp2a_hi(prod[5], wv.z, s);
            s = __dp2a_lo(prod[6], wv.w, s);
            s = __dp2a_hi(prod[7], wv.w, s);
            int rsum = (int)__reduce_add_sync(0xffffffffu, (unsigned)s);
            if (lane == o) s_fc0p[wid * 16 + o] = rsum;
        }
    }
    __syncthreads();

    // ---- warp 1: psqt (only if table nonzero); warp 0: tail MLP ----------
    if (wid == 1) {
        if (g_psq_nz) {
            float ps = 0.f;
            for (int i = lane; i < nw;  i += 32)
                ps += q32f(psq[(size_t)s_wf[i] * 8 + bk]);
            for (int i = lane; i < nbf; i += 32)
                ps -= q32f(psq[(size_t)s_bf[i] * 8 + bk]);
            #pragma unroll
            for (int off = 16; off; off >>= 1)
                ps += __shfl_down_sync(0xffffffffu, ps, off);
            if (lane == 0) s_psqt = (st ? -ps : ps) * 0.5f;
        } else if (lane == 0) {
            s_psqt = 0.f;
        }
    } else {
        // o0
        if (lane < 16) {
            int isum = s_fc0p[lane] + s_fc0p[16 + lane];
            s_o0[lane] = (float)isum * (1.f / 128.f) + q32f(fc0b[bk * 16 + lane]);
        }
        __syncwarp();

        float sl = 0.f;
        if (lane < 15) {
            float v = s_o0[lane];
            sl = clip127(v * v * (1.f / 524288.f));       // 1<<19
        } else if (lane < 30) {
            float v = s_o0[lane - 15];
            sl = clip127(v * (1.f / 64.f));
        }
        s_slab[lane] = sl;
        __syncwarp();

        // fc1: int8 weights, lane's row = 32 B -> 2x LDG.128
        const signed char* w1 = g_fc1q + (bk * 32 + lane) * 32;
        uint4 wa = *reinterpret_cast<const uint4*>(w1);
        uint4 wb = *reinterpret_cast<const uint4*>(w1 + 16);
        const unsigned ww[8] = {wa.x, wa.y, wa.z, wa.w, wb.x, wb.y, wb.z, wb.w};
        float o1 = 0.f;
        #pragma unroll
        for (int q = 0; q < 8; q++) {
            o1 += s_slab[4*q + 0] * sb2f(ww[q], 0);
            o1 += s_slab[4*q + 1] * sb2f(ww[q], 1);
            o1 += s_slab[4*q + 2] * sb2f(ww[q], 2);
            o1 += s_slab[4*q + 3] * sb2f(ww[q], 3);
        }
        o1 += q32f(fc1b[bk * 32 + lane]);

        float a1 = clip127(o1 * (1.f / 64.f));
        float p  = a1 * q8f(fc2w[bk * 32 + lane]);
        #pragma unroll
        for (int off = 16; off; off >>= 1)
            p += __shfl_down_sync(0xffffffffu, p, off);
        if (lane == 0) {
            float scalar = p + q32f(fc2b[bk]);
            float skip   = s_o0[15] * (9600.f / 8128.f);
            s_scalar = scalar + skip;
        }
    }
    __syncthreads();

    if (tid == 0)
        out[b] = (s_psqt + s_scalar) * (1.f / 16.f);
}

extern "C" void kernel_launch(void* const* d_in, const int* in_sizes, int n_in,
                              void* d_out, int out_size)
{
    const int*   wf   = (const int*)d_in[0];
    const int*   wo   = (const int*)d_in[1];
    const int*   bfi  = (const int*)d_in[2];
    const int*   bo   = (const int*)d_in[3];
    const int*   stm  = (const int*)d_in[4];
    const int*   bkt  = (const int*)d_in[5];
    const float* ftw  = (const float*)d_in[6];
    const float* ftb  = (const float*)d_in[7];
    const float* psq  = (const float*)d_in[8];
    const float* f0w  = (const float*)d_in[9];
    const float* f0b  = (const float*)d_in[10];
    const float* f1w  = (const float*)d_in[11];
    const float* f1b  = (const float*)d_in[12];
    const float* f2w  = (const float*)d_in[13];
    const float* f2b  = (const float*)d_in[14];
    float* out = (float*)d_out;

    const int nb = in_sizes[4];
    const int nfeat_total = in_sizes[0];
    const int psq_elems = in_sizes[8];

    cvt_kernel<<<FT_BLOCKS + FC0_BLOCKS + FC1_BLOCKS + 1, 256>>>(ftw, f0w, f1w, ftb);
    psq_flag_kernel<<<1, 1024>>>(psq, psq_elems);

    nnue_kernel<<<nb, 64>>>(wf, wo, bfi, bo, stm, bkt,
                            psq, f0b, f1b, f2w, f2b,
                            out, nfeat_total, nb);
}

// round 12
// speedup vs baseline: 1.4996x; 1.2292x over previous
#include <cuda_runtime.h>
#include <cstdint>

// ---------------------------------------------------------------------------
// GungnirHalfKA (NNUE) batched eval, GB300 sm_103a — Round 10
// R9 + psq-scan folded into cvt (16 leading blocks, partial flags)
//    + cvt 4x float4 per thread (MLP).
// ---------------------------------------------------------------------------

#define FT_IN   45056
#define FT_OUT  1024
#define NB_MAX  8

__device__ signed char g_ftq[(size_t)FT_IN * FT_OUT];   // 46 MB, int8-exact
__device__ signed char g_fc0q[NB_MAX * 16 * FT_OUT];    // 128 KB, int8-exact
__device__ signed char g_fc1q[NB_MAX * 32 * 32];        // 8 KB, int8-exact
__device__ unsigned    g_bq[FT_OUT / 2];                // ft bias, 2x i16 packed
__device__ int         g_psq_part[16];                  // psqt nonzero partials

__device__ __forceinline__ float q8f(float x) {
    return fminf(fmaxf(rintf(x), -128.f), 127.f);
}
__device__ __forceinline__ float q16f(float x) {
    return fminf(fmaxf(rintf(x), -32768.f), 32767.f);
}
__device__ __forceinline__ float q32f(float x) {
    return fminf(fmaxf(rintf(x), -2147483648.f), 2147483647.f);
}
__device__ __forceinline__ float clip127(float x) {
    return fminf(fmaxf(x, 0.f), 127.f);
}

// Widen 4 packed int8 -> 2x(2x int16) and accumulate.
__device__ __forceinline__ void acc4(unsigned* a, unsigned v) {
    unsigned lo, hi;
    asm("prmt.b32 %0, %1, 0, 0x9180;" : "=r"(lo) : "r"(v));
    asm("prmt.b32 %0, %1, 0, 0xB3A2;" : "=r"(hi) : "r"(v));
    a[0] = __vadd2(a[0], lo);
    a[1] = __vadd2(a[1], hi);
}
__device__ __forceinline__ void acc16(unsigned* acc, const int4& v) {
    acc4(acc + 0, (unsigned)v.x);
    acc4(acc + 2, (unsigned)v.y);
    acc4(acc + 4, (unsigned)v.z);
    acc4(acc + 6, (unsigned)v.w);
}

// 4 byte-pair products (u8*u8 <= 16129, fits positive s16) -> 2 packed words.
__device__ __forceinline__ void mulbytes(unsigned a, unsigned c,
                                         int& lo, int& hi) {
    lo = (int)(((a & 0xFFu) * (c & 0xFFu)) |
               ((((a >> 8) & 0xFFu) * ((c >> 8) & 0xFFu)) << 16));
    hi = (int)((((a >> 16) & 0xFFu) * ((c >> 16) & 0xFFu)) |
               (((a >> 24) * (c >> 24)) << 16));
}

// signed byte j of word w -> float
__device__ __forceinline__ float sb2f(unsigned w, int j) {
    return (float)((int)(w << (24 - 8 * j)) >> 24);
}

__device__ __forceinline__ char4 q8x4(const float4& v) {
    char4 c;
    c.x = (signed char)q8f(v.x);
    c.y = (signed char)q8f(v.y);
    c.z = (signed char)q8f(v.z);
    c.w = (signed char)q8f(v.w);
    return c;
}

// ---- cvt grid layout ------------------------------------------------------
// [0, 16)                 : psqt zero-scan partials (runs concurrently)
// [16, 16+FT_CVT)         : ft_weight f32 -> int8, 4 float4/thread
// [.., +FC0_CVT)          : fc0_w  -> int8, 4 float4/thread
// [.., +FC1_CVT)          : fc1_w  -> int8, 4 float4/thread
// last block              : ft_bias -> packed i16
#define SCAN_BLOCKS 16
#define PSQ_F4      (FT_IN * 8 / 4)            /* 90112 float4s  */
#define PSQ_PER_BLK (PSQ_F4 / SCAN_BLOCKS)     /* 5632           */
#define FT_F4       ((size_t)FT_IN * FT_OUT / 4)
#define FT_CVT      (FT_IN / 4)                /* 11264 blocks: 1024 f4 each */
#define FC0_F4      (NB_MAX * 16 * FT_OUT / 4) /* 32768 */
#define FC0_CVT     (FC0_F4 / 1024)            /* 32 */
#define FC1_F4      (NB_MAX * 32 * 32 / 4)     /* 2048 */
#define FC1_CVT     (FC1_F4 / 1024)            /* 2 */
#define CVT_BLOCKS  (SCAN_BLOCKS + FT_CVT + FC0_CVT + FC1_CVT + 1)

__global__ void cvt_kernel(const float* __restrict__ ftw,
                           const float* __restrict__ f0w,
                           const float* __restrict__ f1w,
                           const float* __restrict__ ftb,
                           const float* __restrict__ psq) {
    const int blk = blockIdx.x;
    const int tid = threadIdx.x;

    if (blk < SCAN_BLOCKS) {
        // psqt zero-scan partial: OR over this block's slice, plain store.
        int any = 0;
        const int base = blk * PSQ_PER_BLK;
        #pragma unroll 4
        for (int i = tid; i < PSQ_PER_BLK; i += 256) {
            float4 v = __ldcs(reinterpret_cast<const float4*>(psq) + base + i);
            any |= (v.x != 0.f) | (v.y != 0.f) | (v.z != 0.f) | (v.w != 0.f);
        }
        int r = __syncthreads_or(any);
        if (tid == 0) g_psq_part[blk] = r;
        return;
    }
    int k = blk - SCAN_BLOCKS;
    if (k < FT_CVT) {
        const size_t base = (size_t)k * 1024;
        #pragma unroll
        for (int j = 0; j < 4; j++) {
            size_t i = base + j * 256 + tid;
            float4 v = __ldcs(reinterpret_cast<const float4*>(ftw) + i);
            reinterpret_cast<char4*>(g_ftq)[i] = q8x4(v);
        }
        return;
    }
    k -= FT_CVT;
    if (k < FC0_CVT) {
        const int base = k * 1024;
        #pragma unroll
        for (int j = 0; j < 4; j++) {
            int i = base + j * 256 + tid;
            float4 v = __ldcs(reinterpret_cast<const float4*>(f0w) + i);
            reinterpret_cast<char4*>(g_fc0q)[i] = q8x4(v);
        }
        return;
    }
    k -= FC0_CVT;
    if (k < FC1_CVT) {
        const int base = k * 1024;
        #pragma unroll
        for (int j = 0; j < 4; j++) {
            int i = base + j * 256 + tid;
            float4 v = __ldcs(reinterpret_cast<const float4*>(f1w) + i);
            reinterpret_cast<char4*>(g_fc1q)[i] = q8x4(v);
        }
        return;
    }
    // bias block
    #pragma unroll
    for (int h = 0; h < 2; h++) {
        int w = tid * 2 + h;                   // word 0..511
        int b0 = (int)q16f(ftb[w * 2]);
        int b1 = (int)q16f(ftb[w * 2 + 1]);
        g_bq[w] = (unsigned)(b0 & 0xFFFF) | ((unsigned)b1 << 16);
    }
}

// ---- main fused kernel: one 64-thread CTA per batch item ------------------
__global__ __launch_bounds__(64, 20)
void nnue_kernel(const int* __restrict__ wf,  const int* __restrict__ wo,
                 const int* __restrict__ bf,  const int* __restrict__ bo,
                 const int* __restrict__ stm, const int* __restrict__ bucket,
                 const float* __restrict__ psq,
                 const float* __restrict__ fc0b,
                 const float* __restrict__ fc1b, const float* __restrict__ fc2w,
                 const float* __restrict__ fc2b,
                 float* __restrict__ out, int nfeat_total, int nb)
{
    const int b    = blockIdx.x;
    const int tid  = threadIdx.x;
    const int wid  = tid >> 5;
    const int lane = tid & 31;

    __shared__ __align__(16) int      s_wf[128], s_bf[128];
    __shared__ __align__(16) unsigned s_S[FT_OUT / 4];   // clipped acc_stm u8
    __shared__ __align__(16) unsigned s_O[FT_OUT / 4];   // clipped acc_opp u8
    __shared__ int   s_fc0p[32];                         // per-warp fc0 partials
    __shared__ float s_o0[16];
    __shared__ float s_slab[32];
    __shared__ float s_psqt, s_scalar;
    __shared__ int   s_meta[4];

    if (tid == 0) {
        int ws = wo[b];
        int we = (b + 1 < nb) ? wo[b + 1] : nfeat_total;
        int bs = bo[b];
        int be = (b + 1 < nb) ? bo[b + 1] : nfeat_total;
        s_meta[0] = ws; s_meta[1] = min(we - ws, 128);
        s_meta[2] = bs; s_meta[3] = min(be - bs, 128);
    }
    __syncthreads();
    const int ws  = s_meta[0], nw  = s_meta[1];
    const int bs  = s_meta[2], nbf = s_meta[3];

    for (int i = tid; i < nw;  i += 64) s_wf[i] = wf[ws + i];
    for (int i = tid; i < nbf; i += 64) s_bf[i] = bf[bs + i];
    __syncthreads();

    const int st = stm[b];
    const int bk = bucket[b];
    const int d0 = tid * 16;

    // ---- gather both sides; clip+pack to u8, single STS.128 per side -----
    #pragma unroll
    for (int side = 0; side < 2; side++) {
        const int* feats = side ? s_bf : s_wf;
        const int  n     = side ? nbf  : nw;
        unsigned acc[8] = {0,0,0,0,0,0,0,0};

        int f = 0;
        for (; f + 8 <= n; f += 8) {
            int4 ix0 = *reinterpret_cast<const int4*>(feats + f);
            int4 ix1 = *reinterpret_cast<const int4*>(feats + f + 4);
            int4 v0 = __ldcg(reinterpret_cast<const int4*>(g_ftq + ((size_t)ix0.x << 10) + d0));
            int4 v1 = __ldcg(reinterpret_cast<const int4*>(g_ftq + ((size_t)ix0.y << 10) + d0));
            int4 v2 = __ldcg(reinterpret_cast<const int4*>(g_ftq + ((size_t)ix0.z << 10) + d0));
            int4 v3 = __ldcg(reinterpret_cast<const int4*>(g_ftq + ((size_t)ix0.w << 10) + d0));
            int4 v4 = __ldcg(reinterpret_cast<const int4*>(g_ftq + ((size_t)ix1.x << 10) + d0));
            int4 v5 = __ldcg(reinterpret_cast<const int4*>(g_ftq + ((size_t)ix1.y << 10) + d0));
            int4 v6 = __ldcg(reinterpret_cast<const int4*>(g_ftq + ((size_t)ix1.z << 10) + d0));
            int4 v7 = __ldcg(reinterpret_cast<const int4*>(g_ftq + ((size_t)ix1.w << 10) + d0));
            acc16(acc, v0); acc16(acc, v1); acc16(acc, v2); acc16(acc, v3);
            acc16(acc, v4); acc16(acc, v5); acc16(acc, v6); acc16(acc, v7);
        }
        for (; f < n; f++) {
            const int4 v = __ldcg(reinterpret_cast<const int4*>(
                g_ftq + ((size_t)feats[f] << 10) + d0));
            acc16(acc, v);
        }

        const uint4 bq0 = reinterpret_cast<const uint4*>(g_bq)[tid * 2];
        const uint4 bq1 = reinterpret_cast<const uint4*>(g_bq)[tid * 2 + 1];
        const unsigned biasp[8] = {bq0.x, bq0.y, bq0.z, bq0.w,
                                   bq1.x, bq1.y, bq1.z, bq1.w};

        unsigned pw[4];
        #pragma unroll
        for (int j = 0; j < 4; j++) {
            unsigned a01 = __vadd2(acc[2*j],     biasp[2*j]);
            unsigned a23 = __vadd2(acc[2*j + 1], biasp[2*j + 1]);
            a01 = __vmins2(__vmaxs2(a01, 0u), 0x007F007Fu);
            a23 = __vmins2(__vmaxs2(a23, 0u), 0x007F007Fu);
            pw[j] = __byte_perm(a01, a23, 0x6420);
        }
        unsigned* dst = (side ^ st) ? s_O : s_S;
        reinterpret_cast<uint4*>(dst)[tid] = make_uint4(pw[0], pw[1], pw[2], pw[3]);
    }
    __syncthreads();

    // ---- pairwise products for MY 16 dims, kept in registers -------------
    int prod[8];
    {
        const unsigned* src = (tid < 32) ? s_S : s_O;
        const int tt = tid & 31;
        uint4 A = *reinterpret_cast<const uint4*>(src + 4 * tt);
        uint4 C = *reinterpret_cast<const uint4*>(src + 4 * tt + 128);
        mulbytes(A.x, C.x, prod[0], prod[1]);
        mulbytes(A.y, C.y, prod[2], prod[3]);
        mulbytes(A.z, C.z, prod[4], prod[5]);
        mulbytes(A.w, C.w, prod[6], prod[7]);
    }

    // ---- fc0: all threads, all 16 outputs over own dims; REDUX per warp --
    {
        const signed char* wbase = g_fc0q + (bk << 14) + 16 * tid;
        #pragma unroll
        for (int o = 0; o < 16; o++) {
            int4 wv = *reinterpret_cast<const int4*>(wbase + (o << 10));
            int s = 0;
            s = __dp2a_lo(prod[0], wv.x, s);
            s = __dp2a_hi(prod[1], wv.x, s);
            s = __dp2a_lo(prod[2], wv.y, s);
            s = __dp2a_hi(prod[3], wv.y, s);
            s = __dp2a_lo(prod[4], wv.z, s);
            s = __dp2a_hi(prod[5], wv.z, s);
            s = __dp2a_lo(prod[6], wv.w, s);
            s = __dp2a_hi(prod[7], wv.w, s);
            int rsum = (int)__reduce_add_sync(0xffffffffu, (unsigned)s);
            if (lane == o) s_fc0p[wid * 16 + o] = rsum;
        }
    }
    __syncthreads();

    // ---- warp 1: psqt (only if table nonzero); warp 0: tail MLP ----------
    if (wid == 1) {
        int nzp = (lane < 16) ? g_psq_part[lane] : 0;
        if (__any_sync(0xffffffffu, nzp)) {
            float ps = 0.f;
            for (int i = lane; i < nw;  i += 32)
                ps += q32f(psq[(size_t)s_wf[i] * 8 + bk]);
            for (int i = lane; i < nbf; i += 32)
                ps -= q32f(psq[(size_t)s_bf[i] * 8 + bk]);
            #pragma unroll
            for (int off = 16; off; off >>= 1)
                ps += __shfl_down_sync(0xffffffffu, ps, off);
            if (lane == 0) s_psqt = (st ? -ps : ps) * 0.5f;
        } else if (lane == 0) {
            s_psqt = 0.f;
        }
    } else {
        // o0
        if (lane < 16) {
            int isum = s_fc0p[lane] + s_fc0p[16 + lane];
            s_o0[lane] = (float)isum * (1.f / 128.f) + q32f(fc0b[bk * 16 + lane]);
        }
        __syncwarp();

        float sl = 0.f;
        if (lane < 15) {
            float v = s_o0[lane];
            sl = clip127(v * v * (1.f / 524288.f));       // 1<<19
        } else if (lane < 30) {
            float v = s_o0[lane - 15];
            sl = clip127(v * (1.f / 64.f));
        }
        s_slab[lane] = sl;
        __syncwarp();

        // fc1: int8 weights, lane's row = 32 B -> 2x LDG.128
        const signed char* w1 = g_fc1q + (bk * 32 + lane) * 32;
        uint4 wa = *reinterpret_cast<const uint4*>(w1);
        uint4 wb = *reinterpret_cast<const uint4*>(w1 + 16);
        const unsigned ww[8] = {wa.x, wa.y, wa.z, wa.w, wb.x, wb.y, wb.z, wb.w};
        float o1 = 0.f;
        #pragma unroll
        for (int q = 0; q < 8; q++) {
            o1 += s_slab[4*q + 0] * sb2f(ww[q], 0);
            o1 += s_slab[4*q + 1] * sb2f(ww[q], 1);
            o1 += s_slab[4*q + 2] * sb2f(ww[q], 2);
            o1 += s_slab[4*q + 3] * sb2f(ww[q], 3);
        }
        o1 += q32f(fc1b[bk * 32 + lane]);

        float a1 = clip127(o1 * (1.f / 64.f));
        float p  = a1 * q8f(fc2w[bk * 32 + lane]);
        #pragma unroll
        for (int off = 16; off; off >>= 1)
            p += __shfl_down_sync(0xffffffffu, p, off);
        if (lane == 0) {
            float scalar = p + q32f(fc2b[bk]);
            float skip   = s_o0[15] * (9600.f / 8128.f);
            s_scalar = scalar + skip;
        }
    }
    __syncthreads();

    if (tid == 0)
        out[b] = (s_psqt + s_scalar) * (1.f / 16.f);
}

extern "C" void kernel_launch(void* const* d_in, const int* in_sizes, int n_in,
                              void* d_out, int out_size)
{
    const int*   wf   = (const int*)d_in[0];
    const int*   wo   = (const int*)d_in[1];
    const int*   bfi  = (const int*)d_in[2];
    const int*   bo   = (const int*)d_in[3];
    const int*   stm  = (const int*)d_in[4];
    const int*   bkt  = (const int*)d_in[5];
    const float* ftw  = (const float*)d_in[6];
    const float* ftb  = (const float*)d_in[7];
    const float* psq  = (const float*)d_in[8];
    const float* f0w  = (const float*)d_in[9];
    const float* f0b  = (const float*)d_in[10];
    const float* f1w  = (const float*)d_in[11];
    const float* f1b  = (const float*)d_in[12];
    const float* f2w  = (const float*)d_in[13];
    const float* f2b  = (const float*)d_in[14];
    float* out = (float*)d_out;

    const int nb = in_sizes[4];
    const int nfeat_total = in_sizes[0];

    cvt_kernel<<<CVT_BLOCKS, 256>>>(ftw, f0w, f1w, ftb, psq);

    nnue_kernel<<<nb, 64>>>(wf, wo, bfi, bo, stm, bkt,
                            psq, f0b, f1b, f2w, f2b,
                            out, nfeat_total, nb);
}